// round 7
// baseline (speedup 1.0000x reference)
#include <cuda_runtime.h>
#include <math.h>

// Scratch (device globals; no allocation allowed)
__device__ float g_PEX[32 * 256];        // pos_enc(j) @ W1[0:64]
__device__ float g_PEY[32 * 256];        // pos_enc(r) @ W1[64:128] + b1
__device__ float g_PEB[32 * 256];        // pos_enc(c) @ Wb1[32:96] + bb1
__device__ float g_S  [64];              // row sums of x
__device__ float g_u  [64 * 256];        // u[b,h] = sum_i x[b,i]*h[b,i,h]

__device__ __forceinline__ float tanh_fast(float v) {
    float y;
    asm("tanh.approx.f32 %0, %1;" : "=f"(y) : "f"(v));
    return y;
}

// ---------------------------------------------------------------------------
// K1: positional-encoding projections + row sums. 96 blocks.
// ---------------------------------------------------------------------------
__global__ void k1_setup(const float* __restrict__ x,
                         const float* __restrict__ W1,
                         const float* __restrict__ b1,
                         const float* __restrict__ Wb1,
                         const float* __restrict__ bb1) {
    int blk = blockIdx.x;
    int t = threadIdx.x;

    if (blk < 32) {
        __shared__ float pe[64];
        if (t < 64) {
            int k = t >> 1;
            double invf = exp(-(double)(2 * k) / 64.0 * log(10000.0));
            float ang = (float)((double)blk * invf);
            pe[t] = (t & 1) ? cosf(ang) : sinf(ang);
        }
        __syncthreads();
        float ax = 0.f, ay = 0.f, ab = 0.f;
#pragma unroll
        for (int d = 0; d < 64; d++) {
            float p = pe[d];
            ax = fmaf(p, W1[d * 256 + t], ax);
            ay = fmaf(p, W1[(64 + d) * 256 + t], ay);
            ab = fmaf(p, Wb1[(32 + d) * 256 + t], ab);
        }
        g_PEX[blk * 256 + t] = ax;
        g_PEY[blk * 256 + t] = ay + b1[t];
        g_PEB[blk * 256 + t] = ab + bb1[t];
    } else {
        int b = blk - 32;
        __shared__ float red[256];
        float s = 0.f;
        for (int i = t; i < 1024; i += 256) s += x[b * 1024 + i];
        red[t] = s;
        __syncthreads();
        for (int off = 128; off > 0; off >>= 1) {
            if (t < off) red[t] += red[t + off];
            __syncthreads();
        }
        if (t == 0) g_S[b] = red[0];
    }
}

// ---------------------------------------------------------------------------
// K2: u[b,h] = sum_{r,j} x[b, r*32+j] * tanh(A[j,h] + PEY[r,h])
// A computed cooperatively in smem (W1 slice loaded once per block).
// grid 512 blocks: (b, h-chunk of 32). 256 threads.
// ---------------------------------------------------------------------------
__global__ void k2_u(const float* __restrict__ x,
                     const float* __restrict__ W1) {
    int b = blockIdx.x >> 3;
    int hc = blockIdx.x & 7;
    int t = threadIdx.x;
    int hl = t & 31;
    int rg = t >> 5;
    int h = hc * 32 + hl;

    __shared__ float xs[1024];
    __shared__ float W1s[32][33];
    __shared__ float As[32][33];

    for (int i = t; i < 1024; i += 256) xs[i] = x[b * 1024 + i];
    for (int i = t; i < 1024; i += 256) {
        int c = i >> 5, cl = i & 31;
        W1s[c][cl] = W1[(128 + c) * 256 + hc * 32 + cl];
    }
    __syncthreads();

#pragma unroll
    for (int q = 0; q < 4; q++) {
        int j = rg * 4 + q;
        float a = g_PEX[j * 256 + h];
        const float* xj = &xs[j * 32];
#pragma unroll
        for (int c = 0; c < 32; c++)
            a = fmaf(xj[c], W1s[c][hl], a);
        As[j][hl] = a;
    }
    __syncthreads();

    float A[32];
#pragma unroll
    for (int j = 0; j < 32; j++) A[j] = As[j][hl];

    float acc = 0.f;
#pragma unroll
    for (int rr = 0; rr < 4; rr++) {
        int r = rg * 4 + rr;
        float C = g_PEY[r * 256 + h];
        const float* xr = &xs[r * 32];
#pragma unroll
        for (int j = 0; j < 32; j++)
            acc = fmaf(xr[j], tanh_fast(A[j] + C), acc);
    }

    __shared__ float red[8][33];
    red[rg][hl] = acc;
    __syncthreads();
    if (t < 32) {
        float s = 0.f;
#pragma unroll
        for (int p = 0; p < 8; p++) s += red[p][t];
        g_u[b * 256 + hc * 32 + t] = s;
    }
}

// ---------------------------------------------------------------------------
// K34: fused einsum-output + bias hypernetwork + final add.
// grid 128 blocks: bg (8 batches) x oc (64-output chunk). 256 threads.
// Phase A (k3): out[bb, o] for 8 batches x 64 outputs, kept in smem.
//   = u[b,:] @ W2[:,o] + S[b]*b2[o]    (W2 loaded once, reused x8 batches)
// Phase B (k4): 16 rows (bb, cc): hidden = tanh(os@Wb1[0:32] + PEB), then
//   bias = hidden@Wb2 + bb2; y = os + bias. Register-resident Wb1/Wb2.
// ---------------------------------------------------------------------------
__global__ void __launch_bounds__(256) k34_fused(
        const float* __restrict__ W2,
        const float* __restrict__ b2,
        const float* __restrict__ Wb1,
        const float* __restrict__ Wb2,
        const float* __restrict__ bb2,
        float* __restrict__ y) {
    int bg = blockIdx.x >> 4;     // 0..7
    int oc = blockIdx.x & 15;     // 0..15
    int t = threadIdx.x;

    __shared__ float buf[8192];   // 32KB, aliased between phases
    __shared__ float os[16][32];  // out values: row = bb*2+cc
    __shared__ float Ss[8];

    // ---- Phase A: out = u @ W2 + S*b2 ----
    float* us   = buf;            // [256][8]  u transposed
    float* red4 = buf + 2048;     // [4][8][64]

    int ol = t & 63;
    int hg4 = t >> 6;             // 0..3
    int o = oc * 64 + ol;

    for (int i = t; i < 256 * 8; i += 256) {
        int h = i >> 3, bb = i & 7;
        us[h * 8 + bb] = g_u[(bg * 8 + bb) * 256 + h];
    }
    if (t < 8) Ss[t] = g_S[bg * 8 + t];

    // preload k4 weights (overlaps with phase A latency)
    int hg = t >> 5, m = t & 31;
    float w1[32], w2[32];
#pragma unroll
    for (int k = 0; k < 32; k++) w1[k] = Wb1[k * 256 + t];
#pragma unroll
    for (int hh = 0; hh < 32; hh++) w2[hh] = Wb2[(hg * 32 + hh) * 32 + m];

    __syncthreads();

    float acc[8] = {0.f, 0.f, 0.f, 0.f, 0.f, 0.f, 0.f, 0.f};
#pragma unroll 8
    for (int hh = 0; hh < 64; hh++) {
        int h = hg4 * 64 + hh;
        float w = W2[h * 1024 + o];
        const float* uh = &us[h * 8];
#pragma unroll
        for (int bb = 0; bb < 8; bb++)
            acc[bb] = fmaf(uh[bb], w, acc[bb]);
    }
#pragma unroll
    for (int bb = 0; bb < 8; bb++)
        red4[(hg4 * 8 + bb) * 64 + ol] = acc[bb];
    __syncthreads();

#pragma unroll
    for (int pass = 0; pass < 2; pass++) {
        int bb = hg4 + pass * 4;
        float s = red4[(0 * 8 + bb) * 64 + ol] + red4[(1 * 8 + bb) * 64 + ol]
                + red4[(2 * 8 + bb) * 64 + ol] + red4[(3 * 8 + bb) * 64 + ol];
        s = fmaf(Ss[bb], b2[o], s);
        os[bb * 2 + (ol >> 5)][ol & 31] = s;
    }
    __syncthreads();

    // ---- Phase B: bias hypernetwork over 16 rows ----
    float* H    = buf;            // [16][256]
    float* red8 = buf + 4096;     // [8][16][32]

#pragma unroll
    for (int r = 0; r < 16; r++) {
        int c = oc * 2 + (r & 1);
        float a = g_PEB[c * 256 + t];
        const float4* o4 = (const float4*)os[r];
#pragma unroll
        for (int q = 0; q < 8; q++) {
            float4 ov = o4[q];
            a = fmaf(ov.x, w1[4 * q + 0], a);
            a = fmaf(ov.y, w1[4 * q + 1], a);
            a = fmaf(ov.z, w1[4 * q + 2], a);
            a = fmaf(ov.w, w1[4 * q + 3], a);
        }
        H[r * 256 + t] = tanh_fast(a);
    }
    __syncthreads();

#pragma unroll
    for (int r = 0; r < 16; r++) {
        float s = 0.f;
        const float4* h4 = (const float4*)&H[r * 256 + hg * 32];
#pragma unroll
        for (int q = 0; q < 8; q++) {
            float4 hv = h4[q];
            s = fmaf(hv.x, w2[4 * q + 0], s);
            s = fmaf(hv.y, w2[4 * q + 1], s);
            s = fmaf(hv.z, w2[4 * q + 2], s);
            s = fmaf(hv.w, w2[4 * q + 3], s);
        }
        red8[(hg * 16 + r) * 32 + m] = s;
    }
    __syncthreads();

    // Final: 16 rows x 32 outputs = 512 values, 2 per thread
#pragma unroll
    for (int pass = 0; pass < 2; pass++) {
        int idx = t + pass * 256;
        int r = idx >> 5, mm = idx & 31;
        float bias = bb2[mm];
#pragma unroll
        for (int p = 0; p < 8; p++) bias += red8[(p * 16 + r) * 32 + mm];
        int bb = r >> 1, cc = r & 1;
        y[(bg * 8 + bb) * 1024 + oc * 64 + cc * 32 + mm] = os[r][mm] + bias;
    }
}

extern "C" void kernel_launch(void* const* d_in, const int* in_sizes, int n_in,
                              void* d_out, int out_size) {
    const float* x   = (const float*)d_in[0];
    // d_in[1] = output_size (int) — fixed at 1024 by the problem shapes
    const float* W1  = (const float*)d_in[2];
    const float* b1  = (const float*)d_in[3];
    const float* W2  = (const float*)d_in[4];
    const float* b2  = (const float*)d_in[5];
    const float* Wb1 = (const float*)d_in[6];
    const float* bb1 = (const float*)d_in[7];
    const float* Wb2 = (const float*)d_in[8];
    const float* bb2 = (const float*)d_in[9];
    float* y = (float*)d_out;

    k1_setup<<<96, 256>>>(x, W1, b1, Wb1, bb1);
    k2_u<<<512, 256>>>(x, W1);
    k34_fused<<<128, 256>>>(W2, b2, Wb1, Wb2, bb2, y);
}

// round 9
// speedup vs baseline: 1.2149x; 1.2149x over previous
#include <cuda_runtime.h>
#include <math.h>

// Scratch (device globals; no allocation allowed)
__device__ float g_PEX[32 * 256];        // pos_enc(j) @ W1[0:64]
__device__ float g_PEY[32 * 256];        // pos_enc(r) @ W1[64:128] + b1
__device__ float g_PEB[32 * 256];        // pos_enc(c) @ Wb1[32:96] + bb1
__device__ float g_S  [64];              // row sums of x
__device__ float g_u  [64 * 256];        // u[b,h] = sum_i x[b,i]*h[b,i,h]

__device__ __forceinline__ float tanh_fast(float v) {
    float y;
    asm("tanh.approx.f32 %0, %1;" : "=f"(y) : "f"(v));
    return y;
}

// ---------------------------------------------------------------------------
// K1: positional-encoding projections + row sums. 96 blocks. All fp32.
// blocks [0,32): PEX/PEY/PEB for position p=blk
// blocks [32,96): S[b]
// ---------------------------------------------------------------------------
__global__ void k1_setup(const float* __restrict__ x,
                         const float* __restrict__ W1,
                         const float* __restrict__ b1,
                         const float* __restrict__ Wb1,
                         const float* __restrict__ bb1) {
    int blk = blockIdx.x;
    int t = threadIdx.x;

    if (blk < 32) {
        __shared__ float pe[64];
        if (t < 64) {
            int k = t >> 1;
            // inv_freq = 10000^(-2k/64) = 2^(-(2k/64)*log2(10000))
            float e = -(2.0f * (float)k) * (13.2877123795494f / 64.0f);
            float invf = exp2f(e);
            float ang = (float)blk * invf;
            float s, c;
            sincosf(ang, &s, &c);
            pe[t] = (t & 1) ? c : s;
        }
        __syncthreads();
        float ax = 0.f, ay = 0.f, ab = 0.f;
#pragma unroll
        for (int d = 0; d < 64; d++) {
            float p = pe[d];
            ax = fmaf(p, W1[d * 256 + t], ax);
            ay = fmaf(p, W1[(64 + d) * 256 + t], ay);
            ab = fmaf(p, Wb1[(32 + d) * 256 + t], ab);
        }
        g_PEX[blk * 256 + t] = ax;
        g_PEY[blk * 256 + t] = ay + b1[t];
        g_PEB[blk * 256 + t] = ab + bb1[t];
    } else {
        int b = blk - 32;
        __shared__ float red[256];
        float s = 0.f;
        for (int i = t; i < 1024; i += 256) s += x[b * 1024 + i];
        red[t] = s;
        __syncthreads();
        for (int off = 128; off > 0; off >>= 1) {
            if (t < off) red[t] += red[t + off];
            __syncthreads();
        }
        if (t == 0) g_S[b] = red[0];
    }
}

// ---------------------------------------------------------------------------
// K2: u[b,h] = sum_{r,j} x[b, r*32+j] * tanh(A[j,h] + PEY[r,h])
// A computed cooperatively in smem (W1 slice loaded once per block).
// grid 512 blocks: (b, h-chunk of 32). 256 threads.
// ---------------------------------------------------------------------------
__global__ void k2_u(const float* __restrict__ x,
                     const float* __restrict__ W1) {
    int b = blockIdx.x >> 3;
    int hc = blockIdx.x & 7;
    int t = threadIdx.x;
    int hl = t & 31;
    int rg = t >> 5;
    int h = hc * 32 + hl;

    __shared__ float xs[1024];
    __shared__ float W1s[32][33];
    __shared__ float As[32][33];

    for (int i = t; i < 1024; i += 256) xs[i] = x[b * 1024 + i];
    for (int i = t; i < 1024; i += 256) {
        int c = i >> 5, cl = i & 31;
        W1s[c][cl] = W1[(128 + c) * 256 + hc * 32 + cl];
    }
    __syncthreads();

#pragma unroll
    for (int q = 0; q < 4; q++) {
        int j = rg * 4 + q;
        float a = g_PEX[j * 256 + h];
        const float* xj = &xs[j * 32];
#pragma unroll
        for (int c = 0; c < 32; c++)
            a = fmaf(xj[c], W1s[c][hl], a);
        As[j][hl] = a;
    }
    __syncthreads();

    float A[32];
#pragma unroll
    for (int j = 0; j < 32; j++) A[j] = As[j][hl];

    float acc = 0.f;
#pragma unroll
    for (int rr = 0; rr < 4; rr++) {
        int r = rg * 4 + rr;
        float C = g_PEY[r * 256 + h];
        const float* xr = &xs[r * 32];
#pragma unroll
        for (int j = 0; j < 32; j++)
            acc = fmaf(xr[j], tanh_fast(A[j] + C), acc);
    }

    __shared__ float red[8][33];
    red[rg][hl] = acc;
    __syncthreads();
    if (t < 32) {
        float s = 0.f;
#pragma unroll
        for (int p = 0; p < 8; p++) s += red[p][t];
        g_u[b * 256 + hc * 32 + t] = s;
    }
}

// ---------------------------------------------------------------------------
// K34: fused einsum-output + bias hypernetwork + final add.
// grid 128 blocks: bg (8 batches) x oc (64-output chunk). 256 threads.
// ---------------------------------------------------------------------------
__global__ void __launch_bounds__(256) k34_fused(
        const float* __restrict__ W2,
        const float* __restrict__ b2,
        const float* __restrict__ Wb1,
        const float* __restrict__ Wb2,
        const float* __restrict__ bb2,
        float* __restrict__ y) {
    int bg = blockIdx.x >> 4;     // 0..7
    int oc = blockIdx.x & 15;     // 0..15
    int t = threadIdx.x;

    __shared__ float buf[8192];   // 32KB, aliased between phases
    __shared__ float os[16][32];  // out values: row = bb*2+cc
    __shared__ float Ss[8];

    // ---- Phase A: out = u @ W2 + S*b2 ----
    float* us   = buf;            // [256][8]  u transposed
    float* red4 = buf + 2048;     // [4][8][64]

    int ol = t & 63;
    int hg4 = t >> 6;             // 0..3
    int o = oc * 64 + ol;

    for (int i = t; i < 256 * 8; i += 256) {
        int h = i >> 3, bb = i & 7;
        us[h * 8 + bb] = g_u[(bg * 8 + bb) * 256 + h];
    }
    if (t < 8) Ss[t] = g_S[bg * 8 + t];

    // preload k4 weights (overlaps with phase A latency)
    int hg = t >> 5, m = t & 31;
    float w1[32], w2[32];
#pragma unroll
    for (int k = 0; k < 32; k++) w1[k] = Wb1[k * 256 + t];
#pragma unroll
    for (int hh = 0; hh < 32; hh++) w2[hh] = Wb2[(hg * 32 + hh) * 32 + m];

    __syncthreads();

    float acc[8] = {0.f, 0.f, 0.f, 0.f, 0.f, 0.f, 0.f, 0.f};
#pragma unroll 8
    for (int hh = 0; hh < 64; hh++) {
        int h = hg4 * 64 + hh;
        float w = W2[h * 1024 + o];
        const float* uh = &us[h * 8];
#pragma unroll
        for (int bb = 0; bb < 8; bb++)
            acc[bb] = fmaf(uh[bb], w, acc[bb]);
    }
#pragma unroll
    for (int bb = 0; bb < 8; bb++)
        red4[(hg4 * 8 + bb) * 64 + ol] = acc[bb];
    __syncthreads();

#pragma unroll
    for (int pass = 0; pass < 2; pass++) {
        int bb = hg4 + pass * 4;
        float s = red4[(0 * 8 + bb) * 64 + ol] + red4[(1 * 8 + bb) * 64 + ol]
                + red4[(2 * 8 + bb) * 64 + ol] + red4[(3 * 8 + bb) * 64 + ol];
        s = fmaf(Ss[bb], b2[o], s);
        os[bb * 2 + (ol >> 5)][ol & 31] = s;
    }
    __syncthreads();

    // ---- Phase B: bias hypernetwork over 16 rows ----
    float* H    = buf;            // [16][256]
    float* red8 = buf + 4096;     // [8][16][32]

#pragma unroll
    for (int r = 0; r < 16; r++) {
        int c = oc * 2 + (r & 1);
        float a = g_PEB[c * 256 + t];
        const float4* o4 = (const float4*)os[r];
#pragma unroll
        for (int q = 0; q < 8; q++) {
            float4 ov = o4[q];
            a = fmaf(ov.x, w1[4 * q + 0], a);
            a = fmaf(ov.y, w1[4 * q + 1], a);
            a = fmaf(ov.z, w1[4 * q + 2], a);
            a = fmaf(ov.w, w1[4 * q + 3], a);
        }
        H[r * 256 + t] = tanh_fast(a);
    }
    __syncthreads();

#pragma unroll
    for (int r = 0; r < 16; r++) {
        float s = 0.f;
        const float4* h4 = (const float4*)&H[r * 256 + hg * 32];
#pragma unroll
        for (int q = 0; q < 8; q++) {
            float4 hv = h4[q];
            s = fmaf(hv.x, w2[4 * q + 0], s);
            s = fmaf(hv.y, w2[4 * q + 1], s);
            s = fmaf(hv.z, w2[4 * q + 2], s);
            s = fmaf(hv.w, w2[4 * q + 3], s);
        }
        red8[(hg * 16 + r) * 32 + m] = s;
    }
    __syncthreads();

    // Final: 16 rows x 32 outputs = 512 values, 2 per thread
#pragma unroll
    for (int pass = 0; pass < 2; pass++) {
        int idx = t + pass * 256;
        int r = idx >> 5, mm = idx & 31;
        float bias = bb2[mm];
#pragma unroll
        for (int p = 0; p < 8; p++) bias += red8[(p * 16 + r) * 32 + mm];
        int bb = r >> 1, cc = r & 1;
        y[(bg * 8 + bb) * 1024 + oc * 64 + cc * 32 + mm] = os[r][mm] + bias;
    }
}

extern "C" void kernel_launch(void* const* d_in, const int* in_sizes, int n_in,
                              void* d_out, int out_size) {
    const float* x   = (const float*)d_in[0];
    // d_in[1] = output_size (int) — fixed at 1024 by the problem shapes
    const float* W1  = (const float*)d_in[2];
    const float* b1  = (const float*)d_in[3];
    const float* W2  = (const float*)d_in[4];
    const float* b2  = (const float*)d_in[5];
    const float* Wb1 = (const float*)d_in[6];
    const float* bb1 = (const float*)d_in[7];
    const float* Wb2 = (const float*)d_in[8];
    const float* bb2 = (const float*)d_in[9];
    float* y = (float*)d_out;

    k1_setup<<<96, 256>>>(x, W1, b1, Wb1, bb1);
    k2_u<<<512, 256>>>(x, W1);
    k34_fused<<<128, 256>>>(W2, b2, Wb1, Wb2, bb2, y);
}

// round 11
// speedup vs baseline: 1.2221x; 1.0059x over previous
#include <cuda_runtime.h>
#include <math.h>

// Scratch (device globals; no allocation allowed)
__device__ float g_PEX[32 * 256];        // pos_enc(j) @ W1[0:64]
__device__ float g_PEY[32 * 256];        // pos_enc(r) @ W1[64:128] + b1
__device__ float g_PEB[32 * 256];        // pos_enc(c) @ Wb1[32:96] + bb1
__device__ float g_S  [64];              // row sums of x
__device__ float g_u  [64 * 256];        // u[b,h] = sum_i x[b,i]*h[b,i,h]

__device__ __forceinline__ float tanh_fast(float v) {
    float y;
    asm("tanh.approx.f32 %0, %1;" : "=f"(y) : "f"(v));
    return y;
}

// ---------------------------------------------------------------------------
// K1: positional-encoding projections + row sums. 88 blocks.
// blocks [0,24): (matrix m, h-chunk hc): PE @ W-slice, smem-staged.
//   m=0: PEX = pe @ W1[0:64];  m=1: PEY = pe @ W1[64:128] + b1;
//   m=2: PEB = pe @ Wb1[32:96] + bb1.
// blocks [24,88): S[b] row sums (vectorized).
// ---------------------------------------------------------------------------
__global__ void __launch_bounds__(256) k1_setup(
        const float* __restrict__ x,
        const float* __restrict__ W1,
        const float* __restrict__ b1,
        const float* __restrict__ Wb1,
        const float* __restrict__ bb1) {
    int blk = blockIdx.x;
    int t = threadIdx.x;

    if (blk < 24) {
        int m = blk >> 3;         // matrix id
        int hc = blk & 7;         // h-chunk of 32

        __shared__ float Ws[64][33];   // W slice [d][h-local]
        __shared__ float pes[32][64];  // pe table [pos][d]

        // stage W slice: coalesced, 8 independent LDG per thread
        const float* src = (m == 0) ? (W1 + 0 * 256)
                         : (m == 1) ? (W1 + 64 * 256)
                                    : (Wb1 + 32 * 256);
#pragma unroll
        for (int q = 0; q < 8; q++) {
            int i = t + q * 256;           // 0..2047
            int d = i >> 5, c = i & 31;
            Ws[d][c] = src[d * 256 + hc * 32 + c];
        }

        // build pe table: 4 (pos,k) pairs per thread
#pragma unroll
        for (int q = 0; q < 4; q++) {
            int pi = t + q * 256;          // 0..1023
            int pos = pi >> 5, k = pi & 31;
            float e = -(2.0f * (float)k) * (13.2877123795494f / 64.0f);
            float invf = exp2f(e);
            float ang = (float)pos * invf;
            float s, c;
            sincosf(ang, &s, &c);
            pes[pos][2 * k] = s;
            pes[pos][2 * k + 1] = c;
        }
        __syncthreads();

        int hl = t & 31;          // h-local lane
        int pg = t >> 5;          // position group (4 positions each)
        int h = hc * 32 + hl;

        float acc[4] = {0.f, 0.f, 0.f, 0.f};
#pragma unroll
        for (int d4 = 0; d4 < 16; d4++) {
            float w0 = Ws[d4 * 4 + 0][hl];
            float w1v = Ws[d4 * 4 + 1][hl];
            float w2v = Ws[d4 * 4 + 2][hl];
            float w3 = Ws[d4 * 4 + 3][hl];
#pragma unroll
            for (int p = 0; p < 4; p++) {
                float4 pv = *(const float4*)&pes[pg * 4 + p][d4 * 4];
                acc[p] = fmaf(pv.x, w0, acc[p]);
                acc[p] = fmaf(pv.y, w1v, acc[p]);
                acc[p] = fmaf(pv.z, w2v, acc[p]);
                acc[p] = fmaf(pv.w, w3, acc[p]);
            }
        }

        if (m == 0) {
#pragma unroll
            for (int p = 0; p < 4; p++)
                g_PEX[(pg * 4 + p) * 256 + h] = acc[p];
        } else if (m == 1) {
            float bv = b1[h];
#pragma unroll
            for (int p = 0; p < 4; p++)
                g_PEY[(pg * 4 + p) * 256 + h] = acc[p] + bv;
        } else {
            float bv = bb1[h];
#pragma unroll
            for (int p = 0; p < 4; p++)
                g_PEB[(pg * 4 + p) * 256 + h] = acc[p] + bv;
        }
    } else {
        int b = blk - 24;
        float4 v = ((const float4*)(x + b * 1024))[t];
        float s = v.x + v.y + v.z + v.w;
#pragma unroll
        for (int off = 16; off > 0; off >>= 1)
            s += __shfl_xor_sync(0xffffffffu, s, off);
        __shared__ float red[8];
        if ((t & 31) == 0) red[t >> 5] = s;
        __syncthreads();
        if (t == 0) {
            float tot = 0.f;
#pragma unroll
            for (int p = 0; p < 8; p++) tot += red[p];
            g_S[b] = tot;
        }
    }
}

// ---------------------------------------------------------------------------
// K2: u[b,h] = sum_{r,j} x[b, r*32+j] * tanh(A[j,h] + PEY[r,h])
// A computed cooperatively in smem (W1 slice loaded once per block).
// grid 512 blocks: (b, h-chunk of 32). 256 threads.
// ---------------------------------------------------------------------------
__global__ void k2_u(const float* __restrict__ x,
                     const float* __restrict__ W1) {
    int b = blockIdx.x >> 3;
    int hc = blockIdx.x & 7;
    int t = threadIdx.x;
    int hl = t & 31;
    int rg = t >> 5;
    int h = hc * 32 + hl;

    __shared__ float xs[1024];
    __shared__ float W1s[32][33];
    __shared__ float As[32][33];

    for (int i = t; i < 1024; i += 256) xs[i] = x[b * 1024 + i];
    for (int i = t; i < 1024; i += 256) {
        int c = i >> 5, cl = i & 31;
        W1s[c][cl] = W1[(128 + c) * 256 + hc * 32 + cl];
    }
    __syncthreads();

#pragma unroll
    for (int q = 0; q < 4; q++) {
        int j = rg * 4 + q;
        float a = g_PEX[j * 256 + h];
        const float* xj = &xs[j * 32];
#pragma unroll
        for (int c = 0; c < 32; c++)
            a = fmaf(xj[c], W1s[c][hl], a);
        As[j][hl] = a;
    }
    __syncthreads();

    float A[32];
#pragma unroll
    for (int j = 0; j < 32; j++) A[j] = As[j][hl];

    float acc = 0.f;
#pragma unroll
    for (int rr = 0; rr < 4; rr++) {
        int r = rg * 4 + rr;
        float C = g_PEY[r * 256 + h];
        const float* xr = &xs[r * 32];
#pragma unroll
        for (int j = 0; j < 32; j++)
            acc = fmaf(xr[j], tanh_fast(A[j] + C), acc);
    }

    __shared__ float red[8][33];
    red[rg][hl] = acc;
    __syncthreads();
    if (t < 32) {
        float s = 0.f;
#pragma unroll
        for (int p = 0; p < 8; p++) s += red[p][t];
        g_u[b * 256 + hc * 32 + t] = s;
    }
}

// ---------------------------------------------------------------------------
// K34: fused einsum-output + bias hypernetwork + final add.
// grid 128 blocks: bg (8 batches) x oc (64-output chunk). 256 threads.
// ---------------------------------------------------------------------------
__global__ void __launch_bounds__(256) k34_fused(
        const float* __restrict__ W2,
        const float* __restrict__ b2,
        const float* __restrict__ Wb1,
        const float* __restrict__ Wb2,
        const float* __restrict__ bb2,
        float* __restrict__ y) {
    int bg = blockIdx.x >> 4;     // 0..7
    int oc = blockIdx.x & 15;     // 0..15
    int t = threadIdx.x;

    __shared__ float buf[8192];   // 32KB, aliased between phases
    __shared__ float os[16][32];  // out values: row = bb*2+cc
    __shared__ float Ss[8];

    // ---- Phase A: out = u @ W2 + S*b2 ----
    float* us   = buf;            // [256][8]  u transposed
    float* red4 = buf + 2048;     // [4][8][64]

    int ol = t & 63;
    int hg4 = t >> 6;             // 0..3
    int o = oc * 64 + ol;

    for (int i = t; i < 256 * 8; i += 256) {
        int h = i >> 3, bb = i & 7;
        us[h * 8 + bb] = g_u[(bg * 8 + bb) * 256 + h];
    }
    if (t < 8) Ss[t] = g_S[bg * 8 + t];

    // preload k4 weights (overlaps with phase A latency)
    int hg = t >> 5, m = t & 31;
    float w1[32], w2[32];
#pragma unroll
    for (int k = 0; k < 32; k++) w1[k] = Wb1[k * 256 + t];
#pragma unroll
    for (int hh = 0; hh < 32; hh++) w2[hh] = Wb2[(hg * 32 + hh) * 32 + m];

    __syncthreads();

    float acc[8] = {0.f, 0.f, 0.f, 0.f, 0.f, 0.f, 0.f, 0.f};
#pragma unroll 8
    for (int hh = 0; hh < 64; hh++) {
        int h = hg4 * 64 + hh;
        float w = W2[h * 1024 + o];
        const float* uh = &us[h * 8];
#pragma unroll
        for (int bb = 0; bb < 8; bb++)
            acc[bb] = fmaf(uh[bb], w, acc[bb]);
    }
#pragma unroll
    for (int bb = 0; bb < 8; bb++)
        red4[(hg4 * 8 + bb) * 64 + ol] = acc[bb];
    __syncthreads();

#pragma unroll
    for (int pass = 0; pass < 2; pass++) {
        int bb = hg4 + pass * 4;
        float s = red4[(0 * 8 + bb) * 64 + ol] + red4[(1 * 8 + bb) * 64 + ol]
                + red4[(2 * 8 + bb) * 64 + ol] + red4[(3 * 8 + bb) * 64 + ol];
        s = fmaf(Ss[bb], b2[o], s);
        os[bb * 2 + (ol >> 5)][ol & 31] = s;
    }
    __syncthreads();

    // ---- Phase B: bias hypernetwork over 16 rows ----
    float* H    = buf;            // [16][256]
    float* red8 = buf + 4096;     // [8][16][32]

#pragma unroll
    for (int r = 0; r < 16; r++) {
        int c = oc * 2 + (r & 1);
        float a = g_PEB[c * 256 + t];
        const float4* o4 = (const float4*)os[r];
#pragma unroll
        for (int q = 0; q < 8; q++) {
            float4 ov = o4[q];
            a = fmaf(ov.x, w1[4 * q + 0], a);
            a = fmaf(ov.y, w1[4 * q + 1], a);
            a = fmaf(ov.z, w1[4 * q + 2], a);
            a = fmaf(ov.w, w1[4 * q + 3], a);
        }
        H[r * 256 + t] = tanh_fast(a);
    }
    __syncthreads();

#pragma unroll
    for (int r = 0; r < 16; r++) {
        float s = 0.f;
        const float4* h4 = (const float4*)&H[r * 256 + hg * 32];
#pragma unroll
        for (int q = 0; q < 8; q++) {
            float4 hv = h4[q];
            s = fmaf(hv.x, w2[4 * q + 0], s);
            s = fmaf(hv.y, w2[4 * q + 1], s);
            s = fmaf(hv.z, w2[4 * q + 2], s);
            s = fmaf(hv.w, w2[4 * q + 3], s);
        }
        red8[(hg * 16 + r) * 32 + m] = s;
    }
    __syncthreads();

    // Final: 16 rows x 32 outputs = 512 values, 2 per thread
#pragma unroll
    for (int pass = 0; pass < 2; pass++) {
        int idx = t + pass * 256;
        int r = idx >> 5, mm = idx & 31;
        float bias = bb2[mm];
#pragma unroll
        for (int p = 0; p < 8; p++) bias += red8[(p * 16 + r) * 32 + mm];
        int bb = r >> 1, cc = r & 1;
        y[(bg * 8 + bb) * 1024 + oc * 64 + cc * 32 + mm] = os[r][mm] + bias;
    }
}

extern "C" void kernel_launch(void* const* d_in, const int* in_sizes, int n_in,
                              void* d_out, int out_size) {
    const float* x   = (const float*)d_in[0];
    // d_in[1] = output_size (int) — fixed at 1024 by the problem shapes
    const float* W1  = (const float*)d_in[2];
    const float* b1  = (const float*)d_in[3];
    const float* W2  = (const float*)d_in[4];
    const float* b2  = (const float*)d_in[5];
    const float* Wb1 = (const float*)d_in[6];
    const float* bb1 = (const float*)d_in[7];
    const float* Wb2 = (const float*)d_in[8];
    const float* bb2 = (const float*)d_in[9];
    float* y = (float*)d_out;

    k1_setup<<<88, 256>>>(x, W1, b1, Wb1, bb1);
    k2_u<<<512, 256>>>(x, W1);
    k34_fused<<<128, 256>>>(W2, b2, Wb1, Wb2, bb2, y);
}

// round 12
// speedup vs baseline: 1.4312x; 1.1711x over previous
#include <cuda_runtime.h>
#include <math.h>

// Scratch (device globals; no allocation allowed)
__device__ float g_PEX[32 * 256];        // pos_enc(j) @ W1[0:64]
__device__ float g_PEY[32 * 256];        // pos_enc(r) @ W1[64:128] + b1
__device__ float g_PEB[32 * 256];        // pos_enc(c) @ Wb1[32:96] + bb1
__device__ float g_S  [64];              // row sums of x
__device__ float g_u  [64 * 256];        // u[b,h] = sum_i x[b,i]*h[b,i,h]

__device__ __forceinline__ float tanh_fast(float v) {
    float y;
    asm("tanh.approx.f32 %0, %1;" : "=f"(y) : "f"(v));
    return y;
}

// ---------------------------------------------------------------------------
// K1: positional-encoding projections + row sums. 88 blocks.
// ---------------------------------------------------------------------------
__global__ void __launch_bounds__(256) k1_setup(
        const float* __restrict__ x,
        const float* __restrict__ W1,
        const float* __restrict__ b1,
        const float* __restrict__ Wb1,
        const float* __restrict__ bb1) {
    int blk = blockIdx.x;
    int t = threadIdx.x;

    if (blk < 24) {
        int m = blk >> 3;         // matrix id
        int hc = blk & 7;         // h-chunk of 32

        __shared__ float Ws[64][33];   // W slice [d][h-local]
        __shared__ float pes[32][64];  // pe table [pos][d]

        const float* src = (m == 0) ? (W1 + 0 * 256)
                         : (m == 1) ? (W1 + 64 * 256)
                                    : (Wb1 + 32 * 256);
#pragma unroll
        for (int q = 0; q < 8; q++) {
            int i = t + q * 256;
            int d = i >> 5, c = i & 31;
            Ws[d][c] = src[d * 256 + hc * 32 + c];
        }

#pragma unroll
        for (int q = 0; q < 4; q++) {
            int pi = t + q * 256;
            int pos = pi >> 5, k = pi & 31;
            float e = -(2.0f * (float)k) * (13.2877123795494f / 64.0f);
            float invf = exp2f(e);
            float ang = (float)pos * invf;
            float s, c;
            sincosf(ang, &s, &c);
            pes[pos][2 * k] = s;
            pes[pos][2 * k + 1] = c;
        }
        __syncthreads();

        int hl = t & 31;
        int pg = t >> 5;
        int h = hc * 32 + hl;

        float acc[4] = {0.f, 0.f, 0.f, 0.f};
#pragma unroll
        for (int d4 = 0; d4 < 16; d4++) {
            float w0 = Ws[d4 * 4 + 0][hl];
            float w1v = Ws[d4 * 4 + 1][hl];
            float w2v = Ws[d4 * 4 + 2][hl];
            float w3 = Ws[d4 * 4 + 3][hl];
#pragma unroll
            for (int p = 0; p < 4; p++) {
                float4 pv = *(const float4*)&pes[pg * 4 + p][d4 * 4];
                acc[p] = fmaf(pv.x, w0, acc[p]);
                acc[p] = fmaf(pv.y, w1v, acc[p]);
                acc[p] = fmaf(pv.z, w2v, acc[p]);
                acc[p] = fmaf(pv.w, w3, acc[p]);
            }
        }

        if (m == 0) {
#pragma unroll
            for (int p = 0; p < 4; p++)
                g_PEX[(pg * 4 + p) * 256 + h] = acc[p];
        } else if (m == 1) {
            float bv = b1[h];
#pragma unroll
            for (int p = 0; p < 4; p++)
                g_PEY[(pg * 4 + p) * 256 + h] = acc[p] + bv;
        } else {
            float bv = bb1[h];
#pragma unroll
            for (int p = 0; p < 4; p++)
                g_PEB[(pg * 4 + p) * 256 + h] = acc[p] + bv;
        }
    } else {
        int b = blk - 24;
        float4 v = ((const float4*)(x + b * 1024))[t];
        float s = v.x + v.y + v.z + v.w;
#pragma unroll
        for (int off = 16; off > 0; off >>= 1)
            s += __shfl_xor_sync(0xffffffffu, s, off);
        __shared__ float red[8];
        if ((t & 31) == 0) red[t >> 5] = s;
        __syncthreads();
        if (t == 0) {
            float tot = 0.f;
#pragma unroll
            for (int p = 0; p < 8; p++) tot += red[p];
            g_S[b] = tot;
        }
    }
}

// ---------------------------------------------------------------------------
// K2: u[b,h] = sum_{r,j} x[b, r*32+j] * tanh(A[j,h] + PEY[r,h])
// grid 512 blocks: (b, h-chunk of 32). 256 threads.
// ---------------------------------------------------------------------------
__global__ void k2_u(const float* __restrict__ x,
                     const float* __restrict__ W1) {
    int b = blockIdx.x >> 3;
    int hc = blockIdx.x & 7;
    int t = threadIdx.x;
    int hl = t & 31;
    int rg = t >> 5;
    int h = hc * 32 + hl;

    __shared__ float xs[1024];
    __shared__ float W1s[32][33];
    __shared__ float As[32][33];

    for (int i = t; i < 1024; i += 256) xs[i] = x[b * 1024 + i];
    for (int i = t; i < 1024; i += 256) {
        int c = i >> 5, cl = i & 31;
        W1s[c][cl] = W1[(128 + c) * 256 + hc * 32 + cl];
    }
    __syncthreads();

#pragma unroll
    for (int q = 0; q < 4; q++) {
        int j = rg * 4 + q;
        float a = g_PEX[j * 256 + h];
        const float* xj = &xs[j * 32];
#pragma unroll
        for (int c = 0; c < 32; c++)
            a = fmaf(xj[c], W1s[c][hl], a);
        As[j][hl] = a;
    }
    __syncthreads();

    float A[32];
#pragma unroll
    for (int j = 0; j < 32; j++) A[j] = As[j][hl];

    float acc = 0.f;
#pragma unroll
    for (int rr = 0; rr < 4; rr++) {
        int r = rg * 4 + rr;
        float C = g_PEY[r * 256 + h];
        const float* xr = &xs[r * 32];
#pragma unroll
        for (int j = 0; j < 32; j++)
            acc = fmaf(xr[j], tanh_fast(A[j] + C), acc);
    }

    __shared__ float red[8][33];
    red[rg][hl] = acc;
    __syncthreads();
    if (t < 32) {
        float s = 0.f;
#pragma unroll
        for (int p = 0; p < 8; p++) s += red[p][t];
        g_u[b * 256 + hc * 32 + t] = s;
    }
}

// ---------------------------------------------------------------------------
// K34: fused einsum-output + bias hypernetwork + final add.
// grid 256 blocks: bg (4 batches) x oc (64-output chunk). 256 threads.
// Phase A: out[bb, o] for 4 batches x 64 outputs, kept in smem.
// Phase B: 8 rows (bb, cc) of bias hypernetwork; register-resident Wb1/Wb2.
// ---------------------------------------------------------------------------
__global__ void __launch_bounds__(256) k34_fused(
        const float* __restrict__ W2,
        const float* __restrict__ b2,
        const float* __restrict__ Wb1,
        const float* __restrict__ Wb2,
        const float* __restrict__ bb2,
        float* __restrict__ y) {
    int bg = blockIdx.x >> 4;     // 0..15 (4 batches each)
    int oc = blockIdx.x & 15;     // 0..15 (64-output chunk)
    int t = threadIdx.x;

    __shared__ float buf[4096];   // 16KB, aliased between phases
    __shared__ float os[8][32];   // out values: row = bb*2+cc
    __shared__ float Ss[4];

    // ---- Phase A: out = u @ W2 + S*b2 ----
    float* us   = buf;            // [256][4]  u transposed
    float* red4 = buf + 1024;     // [4][4][64]

    int ol = t & 63;
    int hg4 = t >> 6;             // 0..3
    int o = oc * 64 + ol;

    for (int i = t; i < 256 * 4; i += 256) {
        int h = i >> 2, bb = i & 3;
        us[h * 4 + bb] = g_u[(bg * 4 + bb) * 256 + h];
    }
    if (t < 4) Ss[t] = g_S[bg * 4 + t];

    // preload phase-B weights (overlaps with phase A latency)
    int hg = t >> 5, m = t & 31;
    float w1[32], w2[32];
#pragma unroll
    for (int k = 0; k < 32; k++) w1[k] = Wb1[k * 256 + t];
#pragma unroll
    for (int hh = 0; hh < 32; hh++) w2[hh] = Wb2[(hg * 32 + hh) * 32 + m];

    __syncthreads();

    float acc[4] = {0.f, 0.f, 0.f, 0.f};
#pragma unroll 8
    for (int hh = 0; hh < 64; hh++) {
        int h = hg4 * 64 + hh;
        float w = W2[h * 1024 + o];
        const float* uh = &us[h * 4];
#pragma unroll
        for (int bb = 0; bb < 4; bb++)
            acc[bb] = fmaf(uh[bb], w, acc[bb]);
    }
#pragma unroll
    for (int bb = 0; bb < 4; bb++)
        red4[(hg4 * 4 + bb) * 64 + ol] = acc[bb];
    __syncthreads();

    {
        int bb = t >> 6;          // 0..3
        float s = red4[(0 * 4 + bb) * 64 + ol] + red4[(1 * 4 + bb) * 64 + ol]
                + red4[(2 * 4 + bb) * 64 + ol] + red4[(3 * 4 + bb) * 64 + ol];
        s = fmaf(Ss[bb], b2[o], s);
        os[bb * 2 + (ol >> 5)][ol & 31] = s;
    }
    __syncthreads();

    // ---- Phase B: bias hypernetwork over 8 rows ----
    float* H    = buf;            // [8][256]
    float* red8 = buf + 2048;     // [8][8][32]

#pragma unroll
    for (int r = 0; r < 8; r++) {
        int c = oc * 2 + (r & 1);
        float a = g_PEB[c * 256 + t];
        const float4* o4 = (const float4*)os[r];
#pragma unroll
        for (int q = 0; q < 8; q++) {
            float4 ov = o4[q];
            a = fmaf(ov.x, w1[4 * q + 0], a);
            a = fmaf(ov.y, w1[4 * q + 1], a);
            a = fmaf(ov.z, w1[4 * q + 2], a);
            a = fmaf(ov.w, w1[4 * q + 3], a);
        }
        H[r * 256 + t] = tanh_fast(a);
    }
    __syncthreads();

#pragma unroll
    for (int r = 0; r < 8; r++) {
        float s = 0.f;
        const float4* h4 = (const float4*)&H[r * 256 + hg * 32];
#pragma unroll
        for (int q = 0; q < 8; q++) {
            float4 hv = h4[q];
            s = fmaf(hv.x, w2[4 * q + 0], s);
            s = fmaf(hv.y, w2[4 * q + 1], s);
            s = fmaf(hv.z, w2[4 * q + 2], s);
            s = fmaf(hv.w, w2[4 * q + 3], s);
        }
        red8[(hg * 8 + r) * 32 + m] = s;
    }
    __syncthreads();

    // Final: 8 rows x 32 outputs = 256 values, 1 per thread
    {
        int r = t >> 5, mm = t & 31;
        float bias = bb2[mm];
#pragma unroll
        for (int p = 0; p < 8; p++) bias += red8[(p * 8 + r) * 32 + mm];
        int bb = r >> 1, cc = r & 1;
        y[(bg * 4 + bb) * 1024 + oc * 64 + cc * 32 + mm] = os[r][mm] + bias;
    }
}

extern "C" void kernel_launch(void* const* d_in, const int* in_sizes, int n_in,
                              void* d_out, int out_size) {
    const float* x   = (const float*)d_in[0];
    // d_in[1] = output_size (int) — fixed at 1024 by the problem shapes
    const float* W1  = (const float*)d_in[2];
    const float* b1  = (const float*)d_in[3];
    const float* W2  = (const float*)d_in[4];
    const float* b2  = (const float*)d_in[5];
    const float* Wb1 = (const float*)d_in[6];
    const float* bb1 = (const float*)d_in[7];
    const float* Wb2 = (const float*)d_in[8];
    const float* bb2 = (const float*)d_in[9];
    float* y = (float*)d_out;

    k1_setup<<<88, 256>>>(x, W1, b1, Wb1, bb1);
    k2_u<<<512, 256>>>(x, W1);
    k34_fused<<<256, 256>>>(W2, b2, Wb1, Wb2, bb2, y);
}